// round 5
// baseline (speedup 1.0000x reference)
#include <cuda_runtime.h>
#include <cuda_bf16.h>

// Stencil gather: out[b][j][k][{center,up,right,down,left}] with edge-replicate
// (border neighbor falls back to the center value).
// Input  : [16, 1024, 1024] fp32  (64 MB read)
// Output : [16, 1024, 1024, 5] fp32 (320 MB write)  -> HBM-write-bound.
//
// One block per image row. Adjacent blocks (adjacent rows) are co-resident,
// so the up/down row loads are L2 hits -> DRAM read stays ~64 MB.

#define W 1024
#define H 1024
#define NB 16
#define TPB 256   // 256 threads x 4 pixels (float4) = one full row per block

__global__ __launch_bounds__(TPB, 8)
void stencil5_kernel(const float* __restrict__ x, float* __restrict__ out)
{
    __shared__ float srow[W];   // center row, 16B-aligned float4 stores

    const int row = blockIdx.x;           // 0 .. NB*H-1
    const int j   = row & (H - 1);        // row within image

    const float* crow = x + (size_t)row * W;
    const float* urow = x + (size_t)(j == 0     ? row : row - 1) * W;
    const float* drow = x + (size_t)(j == H - 1 ? row : row + 1) * W;

    const int t = threadIdx.x;
    const int k = t << 2;                 // first pixel this thread owns

    // Coalesced 128B/warp loads of center / up / down rows.
    const float4 c4 = *reinterpret_cast<const float4*>(crow + k);
    const float4 u4 = *reinterpret_cast<const float4*>(urow + k);
    const float4 d4 = *reinterpret_cast<const float4*>(drow + k);

    // Aligned smem stage of the center row (STS.128 at smem_base + 16*t).
    reinterpret_cast<float4*>(srow)[t] = c4;
    __syncthreads();

    // Horizontal neighbors: only the two float4-boundary values need smem.
    // Edge-replicate clamp at k==0 / k==W-1 uses the center value itself.
    const float lft0 = (k == 0)         ? c4.x : srow[k - 1];
    const float rgt3 = (k + 3 == W - 1) ? c4.w : srow[k + 4];

    const float c[4]  = { c4.x, c4.y, c4.z, c4.w };
    const float u[4]  = { u4.x, u4.y, u4.z, u4.w };
    const float dn[4] = { d4.x, d4.y, d4.z, d4.w };
    const float l[4]  = { lft0, c4.x, c4.y, c4.z };
    const float r[4]  = { c4.y, c4.z, c4.w, rgt3 };

    // 20 contiguous output floats for pixels k..k+3.
    // Channel order per pixel: center, up, right, down, left.
    float v[20];
#pragma unroll
    for (int p = 0; p < 4; ++p) {
        v[p * 5 + 0] = c[p];
        v[p * 5 + 1] = u[p];
        v[p * 5 + 2] = r[p];
        v[p * 5 + 3] = dn[p];
        v[p * 5 + 4] = l[p];
    }

    // Output base byte offset: (row*5120 + 20*k/4... ) -> 80*t within the row,
    // 16B-aligned. 5 x STG.128 per thread; a warp writes 2560 contiguous bytes.
    float4* o = reinterpret_cast<float4*>(
        out + (size_t)row * (W * 5) + (size_t)k * 5);
#pragma unroll
    for (int q = 0; q < 5; ++q)
        o[q] = make_float4(v[q * 4 + 0], v[q * 4 + 1],
                           v[q * 4 + 2], v[q * 4 + 3]);
}

extern "C" void kernel_launch(void* const* d_in, const int* in_sizes, int n_in,
                              void* d_out, int out_size)
{
    const float* x = (const float*)d_in[0];
    float* out = (float*)d_out;
    (void)in_sizes; (void)n_in; (void)out_size;

    stencil5_kernel<<<NB * H, TPB>>>(x, out);
}